// round 2
// baseline (speedup 1.0000x reference)
#include <cuda_runtime.h>
#include <cuda_fp16.h>

#define NN 16384
#define KK 1024
#define DD 512
#define ITERS 20
#define HSCALE 16.0f
#define INV_HSCALE (1.0f/16.0f)
#define MU_F (1.0f/16384.0f)
#define NU_F (1.0f/1024.0f)

// ---------------- scratch (static device globals; no runtime allocation) ----------------
__device__ float  g_C[(size_t)NN * KK];     // raw cost matrix (64 MB)
__device__ __half g_Kh[(size_t)NN * KK];    // K_eps * 16 in fp16 (32 MB)
__device__ float  g_u[NN];
__device__ float  g_v[KK];
__device__ float  g_s[KK];
__device__ float  g_dx[NN];
__device__ float  g_dp[KK];
__device__ int    g_cmax_bits;

// ---------------- f32x2 packed-FMA helpers (Blackwell FFMA2 path) ----------------
__device__ __forceinline__ unsigned long long pack2(float lo, float hi) {
    unsigned long long r;
    asm("mov.b64 %0, {%1, %2};" : "=l"(r)
        : "r"(__float_as_uint(lo)), "r"(__float_as_uint(hi)));
    return r;
}
__device__ __forceinline__ void fma2(unsigned long long& d,
                                     unsigned long long a,
                                     unsigned long long b) {
    asm("fma.rn.f32x2 %0, %1, %2, %0;" : "+l"(d) : "l"(a), "l"(b));
}
__device__ __forceinline__ float2 unpack2(unsigned long long v) {
    unsigned lo, hi;
    asm("mov.b64 {%0, %1}, %2;" : "=r"(lo), "=r"(hi) : "l"(v));
    return make_float2(__uint_as_float(lo), __uint_as_float(hi));
}
__device__ __forceinline__ float2 h2f2(unsigned v) {
    __half2 h = *reinterpret_cast<__half2*>(&v);
    return __half22float2(h);
}

// ---------------- init: v = 1, s = 0, cmax = 0, loss slot = 0 ----------------
__global__ void init_kernel(float* __restrict__ out) {
    int t = blockIdx.x * 256 + threadIdx.x;
    if (t < KK) { g_v[t] = 1.0f; g_s[t] = 0.0f; }
    if (t == 0) { g_cmax_bits = 0; out[(size_t)NN * KK] = 0.0f; }  // loss slot
}

// ---------------- row squared norms (D=512, 128 threads/row, one float4 each) ----------------
__global__ void rownorm_kernel(const float* __restrict__ src, int which) {
    int row = blockIdx.x;
    float4 a = reinterpret_cast<const float4*>(src + (size_t)row * DD)[threadIdx.x];
    float v = a.x * a.x + a.y * a.y + a.z * a.z + a.w * a.w;
#pragma unroll
    for (int o = 16; o; o >>= 1) v += __shfl_xor_sync(0xffffffffu, v, o);
    __shared__ float w[4];
    int lane = threadIdx.x & 31, wid = threadIdx.x >> 5;
    if (!lane) w[wid] = v;
    __syncthreads();
    if (threadIdx.x == 0) {
        float s = w[0] + w[1] + w[2] + w[3];
        if (which == 0) g_dx[row] = s; else g_dp[row] = s;
    }
}

// ---------------- GEMM + cost epilogue: C = dx_i + dp_j - 2 * (x @ p^T) ----------------
// 128x128 tile, BK=16, 256 threads, 8x8 microtile, f32x2 packed FMAs.
__global__ __launch_bounds__(256, 1)
void gemm_cost_kernel(const float* __restrict__ x, const float* __restrict__ p) {
    __shared__ __align__(16) float As[16][132];
    __shared__ __align__(16) float Bs[16][132];
    const int tid = threadIdx.x;
    const int bn = blockIdx.x * 128;   // column tile (over K=1024)
    const int bm = blockIdx.y * 128;   // row tile (over N=16384)
    const int tx = tid & 15;
    const int ty = tid >> 4;

    unsigned long long acc2[8][4];
#pragma unroll
    for (int m = 0; m < 8; m++)
#pragma unroll
        for (int n = 0; n < 4; n++) acc2[m][n] = 0ULL;

    for (int k0 = 0; k0 < DD; k0 += 16) {
#pragma unroll
        for (int l = 0; l < 2; l++) {
            int lin = tid + l * 256;
            int r   = lin >> 2;
            int c4  = (lin & 3) * 4;
            float4 a = *reinterpret_cast<const float4*>(x + (size_t)(bm + r) * DD + k0 + c4);
            As[c4 + 0][r] = a.x; As[c4 + 1][r] = a.y;
            As[c4 + 2][r] = a.z; As[c4 + 3][r] = a.w;
            float4 b = *reinterpret_cast<const float4*>(p + (size_t)(bn + r) * DD + k0 + c4);
            Bs[c4 + 0][r] = b.x; Bs[c4 + 1][r] = b.y;
            Bs[c4 + 2][r] = b.z; Bs[c4 + 3][r] = b.w;
        }
        __syncthreads();
#pragma unroll
        for (int kk = 0; kk < 16; kk++) {
            float4 a0 = *reinterpret_cast<const float4*>(&As[kk][ty * 8]);
            float4 a1 = *reinterpret_cast<const float4*>(&As[kk][ty * 8 + 4]);
            unsigned long long aa[8];
            aa[0] = pack2(a0.x, a0.x); aa[1] = pack2(a0.y, a0.y);
            aa[2] = pack2(a0.z, a0.z); aa[3] = pack2(a0.w, a0.w);
            aa[4] = pack2(a1.x, a1.x); aa[5] = pack2(a1.y, a1.y);
            aa[6] = pack2(a1.z, a1.z); aa[7] = pack2(a1.w, a1.w);
            const unsigned long long* bp =
                reinterpret_cast<const unsigned long long*>(&Bs[kk][tx * 8]);
            unsigned long long bb0 = bp[0], bb1 = bp[1], bb2 = bp[2], bb3 = bp[3];
#pragma unroll
            for (int m = 0; m < 8; m++) {
                fma2(acc2[m][0], aa[m], bb0);
                fma2(acc2[m][1], aa[m], bb1);
                fma2(acc2[m][2], aa[m], bb2);
                fma2(acc2[m][3], aa[m], bb3);
            }
        }
        __syncthreads();
    }

    // epilogue: C = dx + dp - 2*G, track block max
    float dxm[8], dpn[8];
#pragma unroll
    for (int m = 0; m < 8; m++) dxm[m] = g_dx[bm + ty * 8 + m];
#pragma unroll
    for (int n = 0; n < 8; n++) dpn[n] = g_dp[bn + tx * 8 + n];

    float tmax = 0.f;
#pragma unroll
    for (int m = 0; m < 8; m++) {
        float r[8];
#pragma unroll
        for (int n2 = 0; n2 < 4; n2++) {
            float2 g = unpack2(acc2[m][n2]);
            r[2 * n2 + 0] = dxm[m] + dpn[2 * n2 + 0] - 2.0f * g.x;
            r[2 * n2 + 1] = dxm[m] + dpn[2 * n2 + 1] - 2.0f * g.y;
            tmax = fmaxf(tmax, fmaxf(r[2 * n2], r[2 * n2 + 1]));
        }
        float* cp = g_C + (size_t)(bm + ty * 8 + m) * KK + bn + tx * 8;
        *reinterpret_cast<float4*>(cp)     = make_float4(r[0], r[1], r[2], r[3]);
        *reinterpret_cast<float4*>(cp + 4) = make_float4(r[4], r[5], r[6], r[7]);
    }
#pragma unroll
    for (int o = 16; o; o >>= 1)
        tmax = fmaxf(tmax, __shfl_xor_sync(0xffffffffu, tmax, o));
    __shared__ float wmax[8];
    int lane = tid & 31, wid = tid >> 5;
    if (!lane) wmax[wid] = tmax;
    __syncthreads();
    if (tid == 0) {
        float mx = wmax[0];
#pragma unroll
        for (int i = 1; i < 8; i++) mx = fmaxf(mx, wmax[i]);
        atomicMax(&g_cmax_bits, __float_as_int(mx));  // all C >= 0, int compare valid
    }
}

// ---------------- K_eps (fp16, x16 scaled): Kh = 16 * exp(-C / ((max+1e-8)*0.1)) ----------------
__global__ void expk_kernel() {
    float negK = -10.0f / (__int_as_float(g_cmax_bits) + 1e-8f);
    size_t nvec = (size_t)NN * KK / 4;
    size_t stride = (size_t)gridDim.x * blockDim.x;
    for (size_t t = (size_t)blockIdx.x * blockDim.x + threadIdx.x; t < nvec; t += stride) {
        float4 c = *reinterpret_cast<const float4*>(g_C + t * 4);
        __half2 h0 = __floats2half2_rn(__expf(c.x * negK) * HSCALE,
                                       __expf(c.y * negK) * HSCALE);
        __half2 h1 = __floats2half2_rn(__expf(c.z * negK) * HSCALE,
                                       __expf(c.w * negK) * HSCALE);
        uint2 pk;
        pk.x = *reinterpret_cast<unsigned*>(&h0);
        pk.y = *reinterpret_cast<unsigned*>(&h1);
        *reinterpret_cast<uint2*>(g_Kh + t * 4) = pk;
    }
}

// ---------------- fused u-step + column-sum: one pass over Kh per iteration ----------------
// 256 threads = 8 warps/block, RPW rows per warp. Each lane owns 32 fixed columns:
// cols (lane + 32q)*8 + i, q in [0,4), i in [0,8). v and col accumulators live in registers.
#define RPW 8
#define ROWS_PER_BLOCK (8 * RPW)   // 64
__global__ __launch_bounds__(256)
void fused_uv_kernel() {
    const int lane = threadIdx.x & 31;
    const int wid  = threadIdx.x >> 5;
    const int rowbase = blockIdx.x * ROWS_PER_BLOCK + wid * RPW;

    // v for this lane's 32 columns -> registers
    float vr[32];
#pragma unroll
    for (int q = 0; q < 4; q++) {
        int e = (lane + 32 * q) * 8;
        float4 a = *reinterpret_cast<const float4*>(g_v + e);
        float4 b = *reinterpret_cast<const float4*>(g_v + e + 4);
        vr[q * 8 + 0] = a.x; vr[q * 8 + 1] = a.y; vr[q * 8 + 2] = a.z; vr[q * 8 + 3] = a.w;
        vr[q * 8 + 4] = b.x; vr[q * 8 + 5] = b.y; vr[q * 8 + 6] = b.z; vr[q * 8 + 7] = b.w;
    }
    float colacc[32];
#pragma unroll
    for (int j = 0; j < 32; j++) colacc[j] = 0.0f;

    for (int r = 0; r < RPW; r++) {
        const int row = rowbase + r;
        const __half* rp = g_Kh + (size_t)row * KK;
        float kh[32];
#pragma unroll
        for (int q = 0; q < 4; q++) {
            int e = (lane + 32 * q) * 8;
            int4 raw = *reinterpret_cast<const int4*>(rp + e);
            float2 f;
            f = h2f2((unsigned)raw.x); kh[q * 8 + 0] = f.x; kh[q * 8 + 1] = f.y;
            f = h2f2((unsigned)raw.y); kh[q * 8 + 2] = f.x; kh[q * 8 + 3] = f.y;
            f = h2f2((unsigned)raw.z); kh[q * 8 + 4] = f.x; kh[q * 8 + 5] = f.y;
            f = h2f2((unsigned)raw.w); kh[q * 8 + 6] = f.x; kh[q * 8 + 7] = f.y;
        }
        float dot = 0.0f;
#pragma unroll
        for (int j = 0; j < 32; j++) dot = fmaf(kh[j], vr[j], dot);
#pragma unroll
        for (int o = 16; o; o >>= 1) dot += __shfl_xor_sync(0xffffffffu, dot, o);
        float u = MU_F / (dot * INV_HSCALE + 1e-8f);
        if (!lane) g_u[row] = u;
#pragma unroll
        for (int j = 0; j < 32; j++) colacc[j] = fmaf(u, kh[j], colacc[j]);
    }

    // block-level reduction of column partials, then one global atomicAdd per col per block
    __shared__ float sm[8][KK];
#pragma unroll
    for (int q = 0; q < 4; q++) {
        int e = (lane + 32 * q) * 8;
        *reinterpret_cast<float4*>(&sm[wid][e]) =
            make_float4(colacc[q * 8 + 0], colacc[q * 8 + 1], colacc[q * 8 + 2], colacc[q * 8 + 3]);
        *reinterpret_cast<float4*>(&sm[wid][e + 4]) =
            make_float4(colacc[q * 8 + 4], colacc[q * 8 + 5], colacc[q * 8 + 6], colacc[q * 8 + 7]);
    }
    __syncthreads();
#pragma unroll
    for (int c = 0; c < 4; c++) {
        int col = threadIdx.x + c * 256;
        float s = sm[0][col];
#pragma unroll
        for (int w = 1; w < 8; w++) s += sm[w][col];
        atomicAdd(&g_s[col], s);
    }
}

// ---------------- v-step: v_j = nu / (s_j / 16 + 1e-8); re-zero s for next iteration ----------------
__global__ void v_kernel() {
    int j = blockIdx.x * 256 + threadIdx.x;
    if (j < KK) {
        g_v[j] = NU_F / (g_s[j] * INV_HSCALE + 1e-8f);
        g_s[j] = 0.0f;
    }
}

// ---------------- final: T = u * exp(-Cn/eps) * v (fp32), loss = sum(T * Cn) ----------------
__global__ __launch_bounds__(256)
void final_kernel(float* __restrict__ out) {
    float invM = 1.0f / (__int_as_float(g_cmax_bits) + 1e-8f);
    size_t nvec = (size_t)NN * KK / 4;
    size_t stride = (size_t)gridDim.x * blockDim.x;
    float lsum = 0.f;
    for (size_t t = (size_t)blockIdx.x * blockDim.x + threadIdx.x; t < nvec; t += stride) {
        size_t base = t * 4;
        int i = (int)(base >> 10);
        int j = (int)(base & 1023);
        float4 c = *reinterpret_cast<const float4*>(g_C + base);
        float4 vj = *reinterpret_cast<const float4*>(g_v + j);
        float ui = g_u[i];
        float cn0 = c.x * invM, cn1 = c.y * invM, cn2 = c.z * invM, cn3 = c.w * invM;
        float t0 = ui * expf(-cn0 * 10.0f) * vj.x;
        float t1 = ui * expf(-cn1 * 10.0f) * vj.y;
        float t2 = ui * expf(-cn2 * 10.0f) * vj.z;
        float t3 = ui * expf(-cn3 * 10.0f) * vj.w;
        *reinterpret_cast<float4*>(out + base) = make_float4(t0, t1, t2, t3);
        lsum += t0 * cn0 + t1 * cn1 + t2 * cn2 + t3 * cn3;
    }
#pragma unroll
    for (int o = 16; o; o >>= 1) lsum += __shfl_xor_sync(0xffffffffu, lsum, o);
    __shared__ float ws[8];
    int lane = threadIdx.x & 31, wid = threadIdx.x >> 5;
    if (!lane) ws[wid] = lsum;
    __syncthreads();
    if (threadIdx.x == 0) {
        float s = 0.f;
#pragma unroll
        for (int i = 0; i < 8; i++) s += ws[i];
        atomicAdd(out + (size_t)NN * KK, s);
    }
}

// ---------------- launch ----------------
extern "C" void kernel_launch(void* const* d_in, const int* in_sizes, int n_in,
                              void* d_out, int out_size) {
    const float* x = (const float*)d_in[0];   // [16384, 512]
    const float* p = (const float*)d_in[1];   // [1024, 512]
    float* out = (float*)d_out;               // T_star [16384,1024] then loss scalar

    init_kernel<<<4, 256>>>(out);
    rownorm_kernel<<<NN, 128>>>(x, 0);
    rownorm_kernel<<<KK, 128>>>(p, 1);
    gemm_cost_kernel<<<dim3(KK / 128, NN / 128), 256>>>(x, p);
    expk_kernel<<<4096, 256>>>();
    for (int it = 0; it < ITERS; it++) {
        fused_uv_kernel<<<NN / ROWS_PER_BLOCK, 256>>>();
        v_kernel<<<4, 256>>>();
    }
    final_kernel<<<2048, 256>>>(out);
}

// round 4
// speedup vs baseline: 1.5078x; 1.5078x over previous
#include <cuda_runtime.h>
#include <cuda_fp16.h>
#include <cuda_bf16.h>
#include <cstdint>

#define NN 16384
#define KK 1024
#define DD 512
#define ITERS 20
#define HSCALE 16.0f
#define INV_HSCALE (1.0f/16.0f)
#define MU_F (1.0f/16384.0f)
#define NU_F (1.0f/1024.0f)

// ---------------- scratch (static device globals; no runtime allocation) ----------------
__device__ float  g_C[(size_t)NN * KK];     // raw cost matrix (64 MB)
__device__ __half g_Kh[(size_t)NN * KK];    // K_eps * 16 in fp16 (32 MB)
__device__ __nv_bfloat16 g_xh[(size_t)NN * DD];
__device__ __nv_bfloat16 g_xl[(size_t)NN * DD];
__device__ __nv_bfloat16 g_ph[(size_t)KK * DD];
__device__ __nv_bfloat16 g_pl[(size_t)KK * DD];
__device__ float  g_u[NN];
__device__ float  g_v[KK];
__device__ float  g_s[KK];
__device__ float  g_dx[NN];
__device__ float  g_dp[KK];
__device__ int    g_cmax_bits;

__device__ __forceinline__ float2 h2f2(unsigned v) {
    __half2 h = *reinterpret_cast<__half2*>(&v);
    return __half22float2(h);
}

__device__ __forceinline__ void cp16(const void* smem_dst, const void* src) {
    uint32_t a;
    asm("{ .reg .u64 t; cvta.to.shared.u64 t, %1; cvt.u32.u64 %0, t; }"
        : "=r"(a) : "l"(smem_dst));
    asm volatile("cp.async.cg.shared.global [%0], [%1], 16;" :: "r"(a), "l"(src));
}

__device__ __forceinline__ void mma_bf16(float* d, const unsigned* a, const unsigned* b) {
    asm volatile(
        "mma.sync.aligned.m16n8k16.row.col.f32.bf16.bf16.f32 "
        "{%0,%1,%2,%3}, {%4,%5,%6,%7}, {%8,%9}, {%0,%1,%2,%3};"
        : "+f"(d[0]), "+f"(d[1]), "+f"(d[2]), "+f"(d[3])
        : "r"(a[0]), "r"(a[1]), "r"(a[2]), "r"(a[3]), "r"(b[0]), "r"(b[1]));
}

// ---------------- init: v = 1, s = 0, cmax = 0, loss slot = 0 ----------------
__global__ void init_kernel(float* __restrict__ out) {
    int t = blockIdx.x * 256 + threadIdx.x;
    if (t < KK) { g_v[t] = 1.0f; g_s[t] = 0.0f; }
    if (t == 0) { g_cmax_bits = 0; out[(size_t)NN * KK] = 0.0f; }
}

// ---------------- split f32 -> bf16 hi/lo + row squared norm ----------------
__global__ void split_kernel(const float* __restrict__ src, int which) {
    int row = blockIdx.x;
    int t = threadIdx.x;  // 128 threads, 4 floats each
    float4 v = reinterpret_cast<const float4*>(src + (size_t)row * DD)[t];

    __nv_bfloat16 h[4], l[4];
    float vv[4] = {v.x, v.y, v.z, v.w};
#pragma unroll
    for (int i = 0; i < 4; i++) {
        h[i] = __float2bfloat16(vv[i]);
        l[i] = __float2bfloat16(vv[i] - __bfloat162float(h[i]));
    }
    __nv_bfloat16* dh = which ? g_ph : g_xh;
    __nv_bfloat16* dl = which ? g_pl : g_xl;
    size_t off = (size_t)row * DD + t * 4;
    *reinterpret_cast<uint2*>(dh + off) = *reinterpret_cast<uint2*>(h);
    *reinterpret_cast<uint2*>(dl + off) = *reinterpret_cast<uint2*>(l);

    float nrm = v.x * v.x + v.y * v.y + v.z * v.z + v.w * v.w;
#pragma unroll
    for (int o = 16; o; o >>= 1) nrm += __shfl_xor_sync(0xffffffffu, nrm, o);
    __shared__ float w[4];
    int lane = t & 31, wid = t >> 5;
    if (!lane) w[wid] = nrm;
    __syncthreads();
    if (t == 0) {
        float s = w[0] + w[1] + w[2] + w[3];
        if (which == 0) g_dx[row] = s; else g_dp[row] = s;
    }
}

// ---------------- HMMA (mma.sync bf16) GEMM + cost epilogue ----------------
// CTA tile 128(M) x 128(N over KK), BK=32, double buffered cp.async.
// 8 warps: warpM = wid&3 (32 rows), warpN = wid>>2 (64 cols).
// bf16 2-term split: G = xh*ph + xh*pl + xl*ph in fp32 accum.
#define BK 32
#define NCHUNK (DD / BK)          // 16
#define ROWB 80                   // bytes per 32-element bf16 row (padded from 64)
#define PARTB (128 * ROWB)        // 10240
#define STAGEB (4 * PARTB)        // 40960: [Ah, Al, Bh, Bl]
#define GEMM_SMEM (2 * STAGEB)    // 81920

__device__ __forceinline__ void load_chunk(char* st, int bm, int bn, int k0, int tid) {
#pragma unroll
    for (int part = 0; part < 4; part++) {
        const __nv_bfloat16* src =
            (part == 0) ? g_xh : (part == 1) ? g_xl : (part == 2) ? g_ph : g_pl;
        const int rbase = (part < 2) ? bm : bn;
        char* dst = st + part * PARTB;
#pragma unroll
        for (int i = 0; i < 2; i++) {
            int g = tid + i * 256;          // 512 granules of 16B per part
            int row = g >> 2, c = g & 3;
            cp16(dst + row * ROWB + c * 16,
                 src + (size_t)(rbase + row) * DD + k0 + c * 8);
        }
    }
}

__global__ __launch_bounds__(256, 1)
void gemm_mma_kernel() {
    extern __shared__ __align__(16) char smem[];
    __shared__ float dpc[128];
    const int tid = threadIdx.x;
    const int wid = tid >> 5, lane = tid & 31;
    const int g = lane >> 2;          // group id 0..7
    const int t2 = (lane & 3) * 2;    // k-pair offset
    const int warpM = wid & 3, warpN = wid >> 2;
    const int bn = blockIdx.x * 128;  // over KK
    const int bm = blockIdx.y * 128;  // over NN

    if (tid < 128) dpc[tid] = g_dp[bn + tid];

    float d[2][8][4];
#pragma unroll
    for (int mi = 0; mi < 2; mi++)
#pragma unroll
        for (int ni = 0; ni < 8; ni++)
#pragma unroll
            for (int q = 0; q < 4; q++) d[mi][ni][q] = 0.0f;

    load_chunk(smem, bm, bn, 0, tid);
    asm volatile("cp.async.commit_group;");

    for (int s = 0; s < NCHUNK; s++) {
        if (s + 1 < NCHUNK) {
            load_chunk(smem + ((s + 1) & 1) * STAGEB, bm, bn, (s + 1) * BK, tid);
            asm volatile("cp.async.commit_group;");
            asm volatile("cp.async.wait_group 1;");
        } else {
            asm volatile("cp.async.wait_group 0;");
        }
        __syncthreads();

        const char* st = smem + (s & 1) * STAGEB;
        const char* Ah = st;
        const char* Al = st + PARTB;
        const char* Bh = st + 2 * PARTB;
        const char* Bl = st + 3 * PARTB;

#pragma unroll
        for (int kb = 0; kb < BK; kb += 16) {
            // A fragments: [part][mi] each 4x b32
            unsigned ah[2][4], al[2][4];
#pragma unroll
            for (int mi = 0; mi < 2; mi++) {
                int r = warpM * 32 + mi * 16 + g;
                const char* pa = Ah + r * ROWB + (kb + t2) * 2;
                ah[mi][0] = *(const unsigned*)(pa);
                ah[mi][1] = *(const unsigned*)(pa + 8 * ROWB);
                ah[mi][2] = *(const unsigned*)(pa + 16);
                ah[mi][3] = *(const unsigned*)(pa + 8 * ROWB + 16);
                const char* pl_ = Al + r * ROWB + (kb + t2) * 2;
                al[mi][0] = *(const unsigned*)(pl_);
                al[mi][1] = *(const unsigned*)(pl_ + 8 * ROWB);
                al[mi][2] = *(const unsigned*)(pl_ + 16);
                al[mi][3] = *(const unsigned*)(pl_ + 8 * ROWB + 16);
            }
#pragma unroll
            for (int ni = 0; ni < 8; ni++) {
                int n = warpN * 64 + ni * 8 + g;
                const char* pb = Bh + n * ROWB + (kb + t2) * 2;
                unsigned bh[2], bl[2];
                bh[0] = *(const unsigned*)(pb);
                bh[1] = *(const unsigned*)(pb + 16);
                const char* pb2 = Bl + n * ROWB + (kb + t2) * 2;
                bl[0] = *(const unsigned*)(pb2);
                bl[1] = *(const unsigned*)(pb2 + 16);
#pragma unroll
                for (int mi = 0; mi < 2; mi++) {
                    mma_bf16(d[mi][ni], ah[mi], bh);
                    mma_bf16(d[mi][ni], ah[mi], bl);
                    mma_bf16(d[mi][ni], al[mi], bh);
                }
            }
        }
        __syncthreads();
    }

    // epilogue: C = dx + dp - 2*G, track max
    float tmax = 0.0f;
#pragma unroll
    for (int mi = 0; mi < 2; mi++) {
#pragma unroll
        for (int h = 0; h < 2; h++) {          // h=0: rows +g, h=1: rows +g+8
            int row = bm + warpM * 32 + mi * 16 + h * 8 + g;
            float dxr = g_dx[row];
            float* cp = g_C + (size_t)row * KK + bn + warpN * 64;
#pragma unroll
            for (int ni = 0; ni < 8; ni++) {
                int c0 = ni * 8 + t2;
                float o0 = dxr + dpc[warpN * 64 + c0]     - 2.0f * d[mi][ni][h * 2];
                float o1 = dxr + dpc[warpN * 64 + c0 + 1] - 2.0f * d[mi][ni][h * 2 + 1];
                tmax = fmaxf(tmax, fmaxf(o0, o1));
                *reinterpret_cast<float2*>(cp + c0) = make_float2(o0, o1);
            }
        }
    }
#pragma unroll
    for (int o = 16; o; o >>= 1)
        tmax = fmaxf(tmax, __shfl_xor_sync(0xffffffffu, tmax, o));
    if (!lane) atomicMax(&g_cmax_bits, __float_as_int(tmax));
}

// ---------------- K_eps (fp16, x16 scaled): Kh = 16 * exp(-C / ((max+1e-8)*0.1)) ----------------
__global__ void expk_kernel() {
    float negK = -10.0f / (__int_as_float(g_cmax_bits) + 1e-8f);
    size_t nvec = (size_t)NN * KK / 4;
    size_t stride = (size_t)gridDim.x * blockDim.x;
    for (size_t t = (size_t)blockIdx.x * blockDim.x + threadIdx.x; t < nvec; t += stride) {
        float4 c = *reinterpret_cast<const float4*>(g_C + t * 4);
        __half2 h0 = __floats2half2_rn(__expf(c.x * negK) * HSCALE,
                                       __expf(c.y * negK) * HSCALE);
        __half2 h1 = __floats2half2_rn(__expf(c.z * negK) * HSCALE,
                                       __expf(c.w * negK) * HSCALE);
        uint2 pk;
        pk.x = *reinterpret_cast<unsigned*>(&h0);
        pk.y = *reinterpret_cast<unsigned*>(&h1);
        *reinterpret_cast<uint2*>(g_Kh + t * 4) = pk;
    }
}

// ---------------- fused u-step + column-sum: one pass over Kh per iteration ----------------
#define RPW 8
#define ROWS_PER_BLOCK (8 * RPW)   // 64
__global__ __launch_bounds__(256)
void fused_uv_kernel() {
    const int lane = threadIdx.x & 31;
    const int wid  = threadIdx.x >> 5;
    const int rowbase = blockIdx.x * ROWS_PER_BLOCK + wid * RPW;

    float vr[32];
#pragma unroll
    for (int q = 0; q < 4; q++) {
        int e = (lane + 32 * q) * 8;
        float4 a = *reinterpret_cast<const float4*>(g_v + e);
        float4 b = *reinterpret_cast<const float4*>(g_v + e + 4);
        vr[q * 8 + 0] = a.x; vr[q * 8 + 1] = a.y; vr[q * 8 + 2] = a.z; vr[q * 8 + 3] = a.w;
        vr[q * 8 + 4] = b.x; vr[q * 8 + 5] = b.y; vr[q * 8 + 6] = b.z; vr[q * 8 + 7] = b.w;
    }
    float colacc[32];
#pragma unroll
    for (int j = 0; j < 32; j++) colacc[j] = 0.0f;

    for (int r = 0; r < RPW; r++) {
        const int row = rowbase + r;
        const __half* rp = g_Kh + (size_t)row * KK;
        float kh[32];
#pragma unroll
        for (int q = 0; q < 4; q++) {
            int e = (lane + 32 * q) * 8;
            int4 raw = *reinterpret_cast<const int4*>(rp + e);
            float2 f;
            f = h2f2((unsigned)raw.x); kh[q * 8 + 0] = f.x; kh[q * 8 + 1] = f.y;
            f = h2f2((unsigned)raw.y); kh[q * 8 + 2] = f.x; kh[q * 8 + 3] = f.y;
            f = h2f2((unsigned)raw.z); kh[q * 8 + 4] = f.x; kh[q * 8 + 5] = f.y;
            f = h2f2((unsigned)raw.w); kh[q * 8 + 6] = f.x; kh[q * 8 + 7] = f.y;
        }
        float dot = 0.0f;
#pragma unroll
        for (int j = 0; j < 32; j++) dot = fmaf(kh[j], vr[j], dot);
#pragma unroll
        for (int o = 16; o; o >>= 1) dot += __shfl_xor_sync(0xffffffffu, dot, o);
        float u = MU_F / (dot * INV_HSCALE + 1e-8f);
        if (!lane) g_u[row] = u;
#pragma unroll
        for (int j = 0; j < 32; j++) colacc[j] = fmaf(u, kh[j], colacc[j]);
    }

    __shared__ float sm[8][KK];
#pragma unroll
    for (int q = 0; q < 4; q++) {
        int e = (lane + 32 * q) * 8;
        *reinterpret_cast<float4*>(&sm[wid][e]) =
            make_float4(colacc[q * 8 + 0], colacc[q * 8 + 1], colacc[q * 8 + 2], colacc[q * 8 + 3]);
        *reinterpret_cast<float4*>(&sm[wid][e + 4]) =
            make_float4(colacc[q * 8 + 4], colacc[q * 8 + 5], colacc[q * 8 + 6], colacc[q * 8 + 7]);
    }
    __syncthreads();
#pragma unroll
    for (int c = 0; c < 4; c++) {
        int col = threadIdx.x + c * 256;
        float s = sm[0][col];
#pragma unroll
        for (int w = 1; w < 8; w++) s += sm[w][col];
        atomicAdd(&g_s[col], s);
    }
}

// ---------------- v-step ----------------
__global__ void v_kernel() {
    int j = blockIdx.x * 256 + threadIdx.x;
    if (j < KK) {
        g_v[j] = NU_F / (g_s[j] * INV_HSCALE + 1e-8f);
        g_s[j] = 0.0f;
    }
}

// ---------------- final: T = u * exp(-Cn/eps) * v, loss = sum(T * Cn) ----------------
__global__ __launch_bounds__(256)
void final_kernel(float* __restrict__ out) {
    float invM = 1.0f / (__int_as_float(g_cmax_bits) + 1e-8f);
    size_t nvec = (size_t)NN * KK / 4;
    size_t stride = (size_t)gridDim.x * blockDim.x;
    float lsum = 0.f;
    for (size_t t = (size_t)blockIdx.x * blockDim.x + threadIdx.x; t < nvec; t += stride) {
        size_t base = t * 4;
        int i = (int)(base >> 10);
        int j = (int)(base & 1023);
        float4 c = *reinterpret_cast<const float4*>(g_C + base);
        float4 vj = *reinterpret_cast<const float4*>(g_v + j);
        float ui = g_u[i];
        float cn0 = c.x * invM, cn1 = c.y * invM, cn2 = c.z * invM, cn3 = c.w * invM;
        float t0 = ui * expf(-cn0 * 10.0f) * vj.x;
        float t1 = ui * expf(-cn1 * 10.0f) * vj.y;
        float t2 = ui * expf(-cn2 * 10.0f) * vj.z;
        float t3 = ui * expf(-cn3 * 10.0f) * vj.w;
        *reinterpret_cast<float4*>(out + base) = make_float4(t0, t1, t2, t3);
        lsum += t0 * cn0 + t1 * cn1 + t2 * cn2 + t3 * cn3;
    }
#pragma unroll
    for (int o = 16; o; o >>= 1) lsum += __shfl_xor_sync(0xffffffffu, lsum, o);
    __shared__ float ws[8];
    int lane = threadIdx.x & 31, wid = threadIdx.x >> 5;
    if (!lane) ws[wid] = lsum;
    __syncthreads();
    if (threadIdx.x == 0) {
        float s = 0.f;
#pragma unroll
        for (int i = 0; i < 8; i++) s += ws[i];
        atomicAdd(out + (size_t)NN * KK, s);
    }
}

// ---------------- launch ----------------
extern "C" void kernel_launch(void* const* d_in, const int* in_sizes, int n_in,
                              void* d_out, int out_size) {
    const float* x = (const float*)d_in[0];   // [16384, 512]
    const float* p = (const float*)d_in[1];   // [1024, 512]
    float* out = (float*)d_out;               // T_star [16384,1024] then loss scalar

    cudaFuncSetAttribute(gemm_mma_kernel,
                         cudaFuncAttributeMaxDynamicSharedMemorySize, GEMM_SMEM);

    init_kernel<<<4, 256>>>(out);
    split_kernel<<<NN, 128>>>(x, 0);
    split_kernel<<<KK, 128>>>(p, 1);
    gemm_mma_kernel<<<dim3(KK / 128, NN / 128), 256, GEMM_SMEM>>>();
    expk_kernel<<<4096, 256>>>();
    for (int it = 0; it < ITERS; it++) {
        fused_uv_kernel<<<NN / ROWS_PER_BLOCK, 256>>>();
        v_kernel<<<4, 256>>>();
    }
    final_kernel<<<2048, 256>>>(out);
}